// round 1
// baseline (speedup 1.0000x reference)
#include <cuda_runtime.h>
#include <cstdint>

// Problem shape (fixed by dataset): x:(32,512,64,64) f32, weight:(1,1,3,3), k=256
#define BB 32
#define NN 512
#define HH 64
#define WW 64
#define IMG_ELEMS (HH * WW)          // 4096
#define SM_STRIDE 65                 // 64 + 1 pad -> conflict-free column walks

// Scratch (no cudaMalloc allowed)
__device__ float2 g_scores[BB * NN];
__device__ int    g_order[BB * NN];

// ---------------------------------------------------------------------------
// Phase 1: per-image conv score with double-float accumulation
// grid = B*N blocks, 128 threads
// ---------------------------------------------------------------------------
__global__ __launch_bounds__(128) void score_kernel(
    const float* __restrict__ x, const float* __restrict__ w,
    float2* __restrict__ scores)
{
    __shared__ float sm[HH * SM_STRIDE];
    __shared__ float2 wsum[4];

    const int t = threadIdx.x;
    const float* img = x + (size_t)blockIdx.x * IMG_ELEMS;

    // Stage image into smem (coalesced float4 reads, stride-65 rows)
    const float4* src = reinterpret_cast<const float4*>(img);
#pragma unroll
    for (int i = 0; i < 8; i++) {
        int f = i * 128 + t;             // float4 index 0..1023
        float4 v = src[f];
        int row = f >> 4;                // 16 float4 per row
        int col = (f & 15) << 2;
        float* p = &sm[row * SM_STRIDE + col];
        p[0] = v.x; p[1] = v.y; p[2] = v.z; p[3] = v.w;
    }

    // Curvature kernel is symmetric: corners w[0], edges w[1], center w[4]
    const float wc = w[0];
    const float wE = w[1];
    const float wm = w[4];

    __syncthreads();

    // Thread mapping: t in [0,62) -> row t, cols [0,31); t in [64,126) -> row t-64, cols [31,62)
    // One row per lane within a warp -> stride-65 column reads are bank-conflict-free.
    float s = 0.f, e = 0.f;
    const bool active = (t < 62) || (t >= 64 && t < 126);
    if (active) {
        const int r  = (t < 62) ? t : (t - 64);
        const int c0 = (t < 62) ? 0 : 31;
        const float* r0p = &sm[r * SM_STRIDE + c0];
        const float* r1p = r0p + SM_STRIDE;
        const float* r2p = r0p + 2 * SM_STRIDE;

        float a0 = r0p[0] + r2p[0], m0 = r1p[0];
        float a1 = r0p[1] + r2p[1], m1 = r1p[1];
#pragma unroll
        for (int j = 0; j < 31; j++) {
            float x0 = r0p[j + 2];
            float x1 = r1p[j + 2];
            float x2 = r2p[j + 2];
            float a2 = x0 + x2;
            float s1 = a0 + a2;
            float s2 = (m0 + x1) + a1;
            float v  = fmaf(wc, s1, fmaf(wE, s2, wm * m1));
            float av = fabsf(v);
            // Fast2Sum compensated accumulate (fp32-exact enough; protected from fast-math)
            float tt  = __fadd_rn(s, av);
            float err = __fadd_rn(__fsub_rn(s, tt), av);
            e = __fadd_rn(e, err);
            s = tt;
            a0 = a1; m0 = m1; a1 = a2; m1 = x1;
        }
    }

    // Warp-level double-float reduction (exact TwoSum)
#pragma unroll
    for (int off = 16; off; off >>= 1) {
        float s2 = __shfl_down_sync(0xffffffffu, s, off);
        float e2 = __shfl_down_sync(0xffffffffu, e, off);
        float tt  = __fadd_rn(s, s2);
        float z   = __fsub_rn(tt, s);
        float err = __fadd_rn(__fsub_rn(s, __fsub_rn(tt, z)), __fsub_rn(s2, z));
        e = __fadd_rn(__fadd_rn(e, e2), err);
        s = tt;
    }
    if ((t & 31) == 0) wsum[t >> 5] = make_float2(s, e);
    __syncthreads();

    if (t == 0) {
        float S = wsum[0].x, E = wsum[0].y;
#pragma unroll
        for (int wi = 1; wi < 4; wi++) {
            float s2 = wsum[wi].x, e2 = wsum[wi].y;
            float tt  = __fadd_rn(S, s2);
            float z   = __fsub_rn(tt, S);
            float err = __fadd_rn(__fsub_rn(S, __fsub_rn(tt, z)), __fsub_rn(s2, z));
            E = __fadd_rn(__fadd_rn(E, e2), err);
            S = tt;
        }
        // Renormalize so lexicographic (hi, lo) compare == value compare
        float h = __fadd_rn(S, E);
        float l = __fadd_rn(__fsub_rn(S, h), E);
        scores[blockIdx.x] = make_float2(h, l);
    }
}

// ---------------------------------------------------------------------------
// Phase 2: exact top-k ranking per batch (descending, ties -> lower index first)
// grid = B blocks, N threads
// ---------------------------------------------------------------------------
__global__ __launch_bounds__(NN) void topk_kernel(
    const float2* __restrict__ scores, int* __restrict__ order, int k)
{
    __shared__ float2 sc[NN];
    const int b = blockIdx.x;
    const int n = threadIdx.x;
    sc[n] = scores[b * NN + n];
    __syncthreads();

    const float2 mine = sc[n];
    int rank = 0;
#pragma unroll 8
    for (int m = 0; m < NN; m++) {
        float2 o = sc[m];
        bool better = (o.x > mine.x) ||
                      (o.x == mine.x && (o.y > mine.y ||
                                         (o.y == mine.y && m < n)));
        rank += better;
    }
    if (rank < k) order[b * k + rank] = n;
}

// ---------------------------------------------------------------------------
// Phase 3: gather selected images
// grid = B*k blocks, 256 threads, float4 copies
// ---------------------------------------------------------------------------
__global__ __launch_bounds__(256) void gather_kernel(
    const float* __restrict__ x, const int* __restrict__ order,
    float* __restrict__ out, int k)
{
    const int bj = blockIdx.x;
    const int b  = bj / k;
    const int n  = order[bj];
    const float4* src = reinterpret_cast<const float4*>(
        x + ((size_t)(b * NN + n)) * IMG_ELEMS);
    float4* dst = reinterpret_cast<float4*>(out + (size_t)bj * IMG_ELEMS);
#pragma unroll
    for (int i = 0; i < 4; i++) {
        dst[threadIdx.x + i * 256] = src[threadIdx.x + i * 256];
    }
}

// ---------------------------------------------------------------------------
extern "C" void kernel_launch(void* const* d_in, const int* in_sizes, int n_in,
                              void* d_out, int out_size)
{
    const float* x = (const float*)d_in[0];
    const float* w = (const float*)d_in[1];
    float* out = (float*)d_out;

    const int k = out_size / (BB * IMG_ELEMS);   // = 256

    score_kernel<<<BB * NN, 128>>>(x, w, g_scores);
    topk_kernel<<<BB, NN>>>(g_scores, g_order, k);
    gather_kernel<<<BB * k, 256>>>(x, g_order, out, k);
}